// round 1
// baseline (speedup 1.0000x reference)
#include <cuda_runtime.h>

// Problem constants
#define B_    32
#define CIN_  128
#define HH_   64
#define WW_   64
#define COUT_ 128
#define NK_   4
#define HID_  32
#define TEMP_ 34.0f
#define KAREA 9   // 3x3

// Scratch (device globals; no allocations allowed)
__device__ float g_att [B_ * NK_];
__device__ float g_aggb[B_ * COUT_];
// Aggregated weights in TRANSPOSED layout for the conv kernel: [b][ci][kk][co]
__device__ __align__(16) float g_aggw[(size_t)B_ * CIN_ * KAREA * COUT_];

// ---------------------------------------------------------------------------
// Kernel A: global-avg-pool -> 2-layer MLP -> softmax(att) -> agg bias
// one block per sample, 256 threads
// ---------------------------------------------------------------------------
__global__ void attn_kernel(const float* __restrict__ x,
                            const float* __restrict__ fc1_w,
                            const float* __restrict__ fc2_w,
                            const float* __restrict__ fc2_b,
                            const float* __restrict__ bias)
{
    __shared__ float ctx[CIN_];
    __shared__ float hid[HID_];
    __shared__ float att[NK_];

    const int b    = blockIdx.x;
    const int tid  = threadIdx.x;
    const int lane = tid & 31;
    const int wid  = tid >> 5;          // 8 warps

    // mean per channel: warp wid handles channels wid*16 .. wid*16+15
    #pragma unroll 1
    for (int j = 0; j < 16; ++j) {
        const int ci = wid * 16 + j;
        const float4* p = (const float4*)(x + ((size_t)(b * CIN_ + ci)) * (HH_ * WW_));
        float s = 0.f;
        #pragma unroll
        for (int it = 0; it < 32; ++it) {
            float4 v = p[lane + it * 32];
            s += v.x + v.y + v.z + v.w;
        }
        #pragma unroll
        for (int o = 16; o > 0; o >>= 1) s += __shfl_down_sync(0xffffffffu, s, o);
        if (lane == 0) ctx[ci] = s * (1.0f / (HH_ * WW_));
    }
    __syncthreads();

    if (tid < HID_) {
        float s = 0.f;
        #pragma unroll 8
        for (int c = 0; c < CIN_; ++c) s += ctx[c] * fc1_w[tid * CIN_ + c];
        hid[tid] = fmaxf(s, 0.f);
    }
    __syncthreads();

    if (tid < NK_) {
        float s = fc2_b[tid];
        #pragma unroll
        for (int i = 0; i < HID_; ++i) s += hid[i] * fc2_w[tid * HID_ + i];
        att[tid] = s * (1.0f / TEMP_);
    }
    __syncthreads();

    if (tid == 0) {
        float m = att[0];
        #pragma unroll
        for (int k = 1; k < NK_; ++k) m = fmaxf(m, att[k]);
        float e[NK_], den = 0.f;
        #pragma unroll
        for (int k = 0; k < NK_; ++k) { e[k] = expf(att[k] - m); den += e[k]; }
        float inv = 1.0f / den;
        #pragma unroll
        for (int k = 0; k < NK_; ++k) {
            att[k] = e[k] * inv;
            g_att[b * NK_ + k] = att[k];
        }
    }
    __syncthreads();

    if (tid < COUT_) {
        float s = 0.f;
        #pragma unroll
        for (int k = 0; k < NK_; ++k) s += att[k] * bias[k * COUT_ + tid];
        g_aggb[b * COUT_ + tid] = s;
    }
}

// ---------------------------------------------------------------------------
// Kernel B: aggregate expert weights into transposed layout [b][ci][kk][co]
// ---------------------------------------------------------------------------
__global__ void aggw_kernel(const float* __restrict__ weight)
{
    const int b = blockIdx.y;
    const int j = blockIdx.x * blockDim.x + threadIdx.x;   // 0 .. CIN*9*COUT-1

    const float a0 = g_att[b * NK_ + 0];
    const float a1 = g_att[b * NK_ + 1];
    const float a2 = g_att[b * NK_ + 2];
    const float a3 = g_att[b * NK_ + 3];

    const int co   = j & (COUT_ - 1);
    const int rest = j >> 7;             // ci*9 + kk
    const int kk   = rest % KAREA;
    const int ci   = rest / KAREA;

    const size_t src = ((size_t)co * CIN_ + ci) * KAREA + kk;  // [co][ci][kk]
    const size_t EX  = (size_t)COUT_ * CIN_ * KAREA;

    float v = a0 * weight[src]
            + a1 * weight[src + EX]
            + a2 * weight[src + 2 * EX]
            + a3 * weight[src + 3 * EX];

    g_aggw[(size_t)b * (CIN_ * KAREA * COUT_) + j] = v;
}

// ---------------------------------------------------------------------------
// Kernel C: per-sample 3x3 conv as tiled GEMM.
// CTA: one sample b, all 128 cout, 128 spatial positions (2 rows of 64).
// Threads 256: ty=tid/16 -> cout block of 8; tx=tid%16 -> (row r, col w0) 8 cols.
// K-loop over ci: x halo tile + 9x128 weight slab in smem, 8x8 register tile.
// ---------------------------------------------------------------------------
__global__ void __launch_bounds__(256, 2)
conv_kernel(const float* __restrict__ x, float* __restrict__ out)
{
    __shared__ __align__(16) float x_s[4][72];          // rows h0-1..h0+2, cols -1..64 at +1
    __shared__ __align__(16) float w_s[KAREA * COUT_];  // [kk][co]

    const int b   = blockIdx.y;
    const int t   = blockIdx.x;      // row-pair tile, 0..31
    const int h0  = t * 2;
    const int tid = threadIdx.x;
    const int ty  = tid >> 4;        // 0..15
    const int tx  = tid & 15;
    const int co0 = ty * 8;
    const int r   = tx >> 3;         // 0..1  (row within pair)
    const int w0  = (tx & 7) * 8;    // column base, 8 cols per thread

    // zero x_s once; halo cells that are never written stay zero for all ci
    for (int i = tid; i < 4 * 72; i += 256) ((float*)x_s)[i] = 0.f;

    float acc[8][8];
    #pragma unroll
    for (int c = 0; c < 8; ++c)
        #pragma unroll
        for (int i = 0; i < 8; ++i) acc[c][i] = 0.f;

    const float* xb = x      + (size_t)b * CIN_ * HH_ * WW_;
    const float* wb = g_aggw + (size_t)b * CIN_ * KAREA * COUT_;

    // x_s interior fill indices (constant across ci)
    const int frr = tid >> 6;        // 0..3
    const int fcc = tid & 63;        // 0..63
    const int fgr = h0 - 1 + frr;    // global row
    const bool fvalid = (fgr >= 0) && (fgr < HH_);

    __syncthreads();

    for (int ci = 0; ci < CIN_; ++ci) {
        // stage x halo tile: 4 rows x 64 interior cols, coalesced
        if (fvalid)
            x_s[frr][fcc + 1] = xb[((size_t)ci * HH_ + fgr) * WW_ + fcc];

        // stage weights: contiguous 1152 floats = 288 float4
        {
            const float4* src = (const float4*)(wb + (size_t)ci * (KAREA * COUT_));
            float4* dst = (float4*)w_s;
            dst[tid] = src[tid];
            if (tid < 32) dst[256 + tid] = src[256 + tid];
        }
        __syncthreads();

        #pragma unroll
        for (int kh = 0; kh < 3; ++kh) {
            float xv[10];
            const float* xr = &x_s[r + kh][w0];
            float4 p0 = *(const float4*)(xr);
            float4 p1 = *(const float4*)(xr + 4);
            xv[0] = p0.x; xv[1] = p0.y; xv[2] = p0.z; xv[3] = p0.w;
            xv[4] = p1.x; xv[5] = p1.y; xv[6] = p1.z; xv[7] = p1.w;
            xv[8] = xr[8]; xv[9] = xr[9];

            #pragma unroll
            for (int kw = 0; kw < 3; ++kw) {
                const float* wrow = &w_s[(kh * 3 + kw) * COUT_ + co0];
                float4 q0 = *(const float4*)(wrow);
                float4 q1 = *(const float4*)(wrow + 4);
                float wr[8] = {q0.x, q0.y, q0.z, q0.w, q1.x, q1.y, q1.z, q1.w};
                #pragma unroll
                for (int c = 0; c < 8; ++c)
                    #pragma unroll
                    for (int i = 0; i < 8; ++i)
                        acc[c][i] = fmaf(wr[c], xv[i + kw], acc[c][i]);
            }
        }
        __syncthreads();
    }

    // epilogue: add aggregated bias, vectorized store
    const int row = h0 + r;
    #pragma unroll
    for (int c = 0; c < 8; ++c) {
        const int co = co0 + c;
        const float bv = g_aggb[b * COUT_ + co];
        float* op = out + (((size_t)(b * COUT_ + co)) * HH_ + row) * WW_ + w0;
        float4 o0 = {acc[c][0] + bv, acc[c][1] + bv, acc[c][2] + bv, acc[c][3] + bv};
        float4 o1 = {acc[c][4] + bv, acc[c][5] + bv, acc[c][6] + bv, acc[c][7] + bv};
        *(float4*)(op)     = o0;
        *(float4*)(op + 4) = o1;
    }
}

// ---------------------------------------------------------------------------
extern "C" void kernel_launch(void* const* d_in, const int* in_sizes, int n_in,
                              void* d_out, int out_size)
{
    const float* x      = (const float*)d_in[0];  // [32,128,64,64]
    const float* fc1_w  = (const float*)d_in[1];  // [32,128]
    const float* fc2_w  = (const float*)d_in[2];  // [4,32]
    const float* fc2_b  = (const float*)d_in[3];  // [4]
    const float* weight = (const float*)d_in[4];  // [4,128,128,3,3]
    const float* bias   = (const float*)d_in[5];  // [4,128]
    float* out = (float*)d_out;                    // [32,128,64,64]

    attn_kernel<<<B_, 256>>>(x, fc1_w, fc2_w, fc2_b, bias);

    const int per_sample = CIN_ * KAREA * COUT_;   // 147456
    aggw_kernel<<<dim3(per_sample / 256, B_), 256>>>(weight);

    conv_kernel<<<dim3(HH_ / 2, B_), 256>>>(x, out);
}

// round 2
// speedup vs baseline: 1.2489x; 1.2489x over previous
#include <cuda_runtime.h>

// Problem constants
#define B_    32
#define CIN_  128
#define HH_   64
#define WW_   64
#define COUT_ 128
#define NK_   4
#define HID_  32
#define TEMP_ 34.0f
#define KAREA 9   // 3x3

// Scratch (device globals; no allocations allowed)
__device__ float g_ctx [B_ * CIN_];
__device__ float g_att [B_ * NK_];
__device__ float g_aggb[B_ * COUT_];
// Aggregated weights, layout [b][ci*9+kk][co]
__device__ __align__(16) float g_aggw[(size_t)B_ * CIN_ * KAREA * COUT_];

// ---------------------------------------------------------------------------
// packed fp32x2 helpers (sm_103a)
// ---------------------------------------------------------------------------
__device__ __forceinline__ unsigned long long bcast2(float v) {
    unsigned long long r;
    asm("mov.b64 %0, {%1, %1};" : "=l"(r) : "r"(__float_as_uint(v)));
    return r;
}
__device__ __forceinline__ unsigned long long fma2(unsigned long long a,
                                                   unsigned long long b,
                                                   unsigned long long c) {
    unsigned long long d;
    asm("fma.rn.f32x2 %0, %1, %2, %3;" : "=l"(d) : "l"(a), "l"(b), "l"(c));
    return d;
}
__device__ __forceinline__ void unpack2(unsigned long long v, float& lo, float& hi) {
    unsigned int ul, uh;
    asm("mov.b64 {%0, %1}, %2;" : "=r"(ul), "=r"(uh) : "l"(v));
    lo = __uint_as_float(ul);
    hi = __uint_as_float(uh);
}

// ---------------------------------------------------------------------------
// Kernel A1: global average pool, one CTA per (b, ci)  -> g_ctx
// ---------------------------------------------------------------------------
__global__ void pool_kernel(const float* __restrict__ x)
{
    const int bc = blockIdx.x;                  // b*CIN_ + ci
    const float4* p = (const float4*)(x + (size_t)bc * (HH_ * WW_));
    float s = 0.f;
    #pragma unroll
    for (int i = 0; i < 8; ++i) {
        float4 v = p[threadIdx.x + (i << 7)];
        s += (v.x + v.y) + (v.z + v.w);
    }
    #pragma unroll
    for (int o = 16; o > 0; o >>= 1) s += __shfl_down_sync(0xffffffffu, s, o);
    __shared__ float ws[4];
    const int lane = threadIdx.x & 31, wid = threadIdx.x >> 5;
    if (lane == 0) ws[wid] = s;
    __syncthreads();
    if (threadIdx.x == 0)
        g_ctx[bc] = (ws[0] + ws[1] + ws[2] + ws[3]) * (1.0f / (HH_ * WW_));
}

// ---------------------------------------------------------------------------
// Kernel A2: MLP -> softmax -> att + aggregated bias. one CTA per sample.
// ---------------------------------------------------------------------------
__global__ void mlp_kernel(const float* __restrict__ fc1_w,
                           const float* __restrict__ fc2_w,
                           const float* __restrict__ fc2_b,
                           const float* __restrict__ bias)
{
    __shared__ float ctx[CIN_];
    __shared__ float hid[HID_];
    __shared__ float att[NK_];

    const int b   = blockIdx.x;
    const int tid = threadIdx.x;   // 128 threads

    ctx[tid] = g_ctx[b * CIN_ + tid];
    __syncthreads();

    if (tid < HID_) {
        float s = 0.f;
        #pragma unroll 8
        for (int c = 0; c < CIN_; ++c) s += ctx[c] * fc1_w[tid * CIN_ + c];
        hid[tid] = fmaxf(s, 0.f);
    }
    __syncthreads();

    if (tid < NK_) {
        float s = fc2_b[tid];
        #pragma unroll
        for (int i = 0; i < HID_; ++i) s += hid[i] * fc2_w[tid * HID_ + i];
        att[tid] = s * (1.0f / TEMP_);
    }
    __syncthreads();

    if (tid == 0) {
        float m = att[0];
        #pragma unroll
        for (int k = 1; k < NK_; ++k) m = fmaxf(m, att[k]);
        float e[NK_], den = 0.f;
        #pragma unroll
        for (int k = 0; k < NK_; ++k) { e[k] = expf(att[k] - m); den += e[k]; }
        float inv = 1.0f / den;
        #pragma unroll
        for (int k = 0; k < NK_; ++k) {
            att[k] = e[k] * inv;
            g_att[b * NK_ + k] = att[k];
        }
    }
    __syncthreads();

    {
        float s = 0.f;
        #pragma unroll
        for (int k = 0; k < NK_; ++k) s += att[k] * bias[k * COUT_ + tid];
        g_aggb[b * COUT_ + tid] = s;
    }
}

// ---------------------------------------------------------------------------
// Kernel B: weight aggregation + transpose via SMEM tiles.
// Reads coalesced along the contiguous [ci][kk] dim of weight[e][co][ci][kk],
// writes coalesced along co of g_aggw[b][cik][co].
// grid (36, 4, 32), block 256.
// ---------------------------------------------------------------------------
__global__ void aggw_kernel(const float* __restrict__ weight)
{
    __shared__ float tile[32][33];
    const int b    = blockIdx.z;
    const int cik0 = blockIdx.x * 32;    // over CIN_*KAREA = 1152
    const int co0  = blockIdx.y * 32;
    const int w    = threadIdx.x >> 5;   // 0..7
    const int lane = threadIdx.x & 31;

    const float a0 = g_att[b * NK_ + 0];
    const float a1 = g_att[b * NK_ + 1];
    const float a2 = g_att[b * NK_ + 2];
    const float a3 = g_att[b * NK_ + 3];

    const size_t EX = (size_t)COUT_ * CIN_ * KAREA;   // 147456 per expert

    #pragma unroll
    for (int rr = 0; rr < 4; ++rr) {
        const int co = co0 + w * 4 + rr;
        const size_t src = (size_t)co * (CIN_ * KAREA) + cik0 + lane;
        float v = a0 * weight[src]
                + a1 * weight[src + EX]
                + a2 * weight[src + 2 * EX]
                + a3 * weight[src + 3 * EX];
        tile[w * 4 + rr][lane] = v;
    }
    __syncthreads();
    #pragma unroll
    for (int rr = 0; rr < 4; ++rr) {
        const int cikl = w * 4 + rr;
        g_aggw[((size_t)b * (CIN_ * KAREA) + cik0 + cikl) * COUT_ + co0 + lane] =
            tile[lane][cikl];
    }
}

// ---------------------------------------------------------------------------
// Kernel C: per-sample 3x3 conv, register-blocked, packed f32x2 FMA.
// CTA: (sample b, 2 output rows), 128 cout x 128 positions.
// Thread: 8 cout (as 4 f32x2 pairs) x 8 columns.
// ---------------------------------------------------------------------------
__global__ void __launch_bounds__(256, 2)
conv_kernel(const float* __restrict__ x, float* __restrict__ out)
{
    __shared__ __align__(16) float x_s[4][72];          // rows h0-1..h0+2, col -1 at idx 0
    __shared__ __align__(16) float w_s[KAREA * COUT_];  // [kk][co]

    const int b   = blockIdx.y;
    const int h0  = blockIdx.x * 2;
    const int tid = threadIdx.x;
    const int ty  = tid >> 4;        // 0..15
    const int tx  = tid & 15;
    const int co0 = ty * 8;
    const int r   = tx >> 3;         // row within pair
    const int w0  = (tx & 7) * 8;    // column base

    for (int i = tid; i < 4 * 72; i += 256) ((float*)x_s)[i] = 0.f;

    unsigned long long acc2[4][8];   // [cout-pair][col]
    #pragma unroll
    for (int c = 0; c < 4; ++c)
        #pragma unroll
        for (int i = 0; i < 8; ++i) acc2[c][i] = 0ull;

    const float* xb = x      + (size_t)b * CIN_ * HH_ * WW_;
    const float* wb = g_aggw + (size_t)b * CIN_ * KAREA * COUT_;

    const int frr = tid >> 6;        // 0..3
    const int fcc = tid & 63;        // 0..63
    const int fgr = h0 - 1 + frr;
    const bool fvalid = (fgr >= 0) && (fgr < HH_);

    __syncthreads();

    for (int ci = 0; ci < CIN_; ++ci) {
        if (fvalid)
            x_s[frr][fcc + 1] = xb[((size_t)ci * HH_ + fgr) * WW_ + fcc];
        {
            const float4* src = (const float4*)(wb + (size_t)ci * (KAREA * COUT_));
            float4* dst = (float4*)w_s;
            dst[tid] = src[tid];
            if (tid < 32) dst[256 + tid] = src[256 + tid];
        }
        __syncthreads();

        #pragma unroll
        for (int kh = 0; kh < 3; ++kh) {
            const float* xr = &x_s[r + kh][w0];
            float4 p0 = *(const float4*)(xr);
            float4 p1 = *(const float4*)(xr + 4);
            unsigned long long xb2[10];
            xb2[0] = bcast2(p0.x); xb2[1] = bcast2(p0.y);
            xb2[2] = bcast2(p0.z); xb2[3] = bcast2(p0.w);
            xb2[4] = bcast2(p1.x); xb2[5] = bcast2(p1.y);
            xb2[6] = bcast2(p1.z); xb2[7] = bcast2(p1.w);
            xb2[8] = bcast2(xr[8]); xb2[9] = bcast2(xr[9]);

            #pragma unroll
            for (int kw = 0; kw < 3; ++kw) {
                const unsigned long long* wrow =
                    (const unsigned long long*)&w_s[(kh * 3 + kw) * COUT_ + co0];
                unsigned long long w2[4] = {wrow[0], wrow[1], wrow[2], wrow[3]};
                #pragma unroll
                for (int c = 0; c < 4; ++c)
                    #pragma unroll
                    for (int i = 0; i < 8; ++i)
                        acc2[c][i] = fma2(w2[c], xb2[i + kw], acc2[c][i]);
            }
        }
        __syncthreads();
    }

    // epilogue: unpack pairs, add bias, vectorized stores
    const int row = h0 + r;
    #pragma unroll
    for (int c = 0; c < 4; ++c) {
        const int coA = co0 + 2 * c;
        const int coB = coA + 1;
        const float bA = g_aggb[b * COUT_ + coA];
        const float bB = g_aggb[b * COUT_ + coB];
        float lo[8], hi[8];
        #pragma unroll
        for (int i = 0; i < 8; ++i) unpack2(acc2[c][i], lo[i], hi[i]);

        float* opA = out + (((size_t)(b * COUT_ + coA)) * HH_ + row) * WW_ + w0;
        float* opB = out + (((size_t)(b * COUT_ + coB)) * HH_ + row) * WW_ + w0;
        float4 a0 = {lo[0] + bA, lo[1] + bA, lo[2] + bA, lo[3] + bA};
        float4 a1 = {lo[4] + bA, lo[5] + bA, lo[6] + bA, lo[7] + bA};
        float4 b0 = {hi[0] + bB, hi[1] + bB, hi[2] + bB, hi[3] + bB};
        float4 b1 = {hi[4] + bB, hi[5] + bB, hi[6] + bB, hi[7] + bB};
        *(float4*)(opA)     = a0;
        *(float4*)(opA + 4) = a1;
        *(float4*)(opB)     = b0;
        *(float4*)(opB + 4) = b1;
    }
}

// ---------------------------------------------------------------------------
extern "C" void kernel_launch(void* const* d_in, const int* in_sizes, int n_in,
                              void* d_out, int out_size)
{
    const float* x      = (const float*)d_in[0];  // [32,128,64,64]
    const float* fc1_w  = (const float*)d_in[1];  // [32,128]
    const float* fc2_w  = (const float*)d_in[2];  // [4,32]
    const float* fc2_b  = (const float*)d_in[3];  // [4]
    const float* weight = (const float*)d_in[4];  // [4,128,128,3,3]
    const float* bias   = (const float*)d_in[5];  // [4,128]
    float* out = (float*)d_out;                    // [32,128,64,64]

    pool_kernel<<<B_ * CIN_, 128>>>(x);
    mlp_kernel<<<B_, 128>>>(fc1_w, fc2_w, fc2_b, bias);
    aggw_kernel<<<dim3(36, 4, B_), 256>>>(weight);
    conv_kernel<<<dim3(HH_ / 2, B_), 256>>>(x, out);
}

// round 4
// speedup vs baseline: 2.4802x; 1.9858x over previous
#include <cuda_runtime.h>
#include <cuda_bf16.h>
#include <cstdint>

// Problem constants
#define B_    32
#define CIN_  128
#define HH_   64
#define WW_   64
#define COUT_ 128
#define NK_   4
#define HID_  32
#define TEMP_ 34.0f

// ---------------------------------------------------------------------------
// Device scratch
// ---------------------------------------------------------------------------
__device__ float g_ctx [B_ * CIN_];
__device__ float g_att [B_ * NK_];
__device__ float g_aggb[B_ * COUT_];
// Aggregated weights, bf16 hi/lo planes, layout [b][chunk(4)][tap(9)][co(128)][ci(32)]
__device__ __align__(16) __nv_bfloat16 g_wa_hi[(size_t)B_ * 4 * 9 * 128 * 32];
__device__ __align__(16) __nv_bfloat16 g_wa_lo[(size_t)B_ * 4 * 9 * 128 * 32];

// ---------------------------------------------------------------------------
// mma.sync m16n8k16 row.col f32.bf16.bf16.f32 (family-common PTX, sm_80+)
// ---------------------------------------------------------------------------
__device__ __forceinline__ void mma_bf16(float* d, const uint32_t* a, const uint32_t* b) {
    asm volatile(
        "mma.sync.aligned.m16n8k16.row.col.f32.bf16.bf16.f32 "
        "{%0,%1,%2,%3}, {%4,%5,%6,%7}, {%8,%9}, {%0,%1,%2,%3};"
        : "+f"(d[0]), "+f"(d[1]), "+f"(d[2]), "+f"(d[3])
        : "r"(a[0]), "r"(a[1]), "r"(a[2]), "r"(a[3]), "r"(b[0]), "r"(b[1]));
}

__device__ __forceinline__ uint32_t pack_bf16x2(__nv_bfloat16 lo, __nv_bfloat16 hi) {
    return (uint32_t)__bfloat16_as_ushort(lo) | ((uint32_t)__bfloat16_as_ushort(hi) << 16);
}

// ---------------------------------------------------------------------------
// Kernel A1: global average pool -> g_ctx
// ---------------------------------------------------------------------------
__global__ void pool_kernel(const float* __restrict__ x)
{
    const int bc = blockIdx.x;
    const float4* p = (const float4*)(x + (size_t)bc * (HH_ * WW_));
    float s = 0.f;
    #pragma unroll
    for (int i = 0; i < 8; ++i) {
        float4 v = p[threadIdx.x + (i << 7)];
        s += (v.x + v.y) + (v.z + v.w);
    }
    #pragma unroll
    for (int o = 16; o > 0; o >>= 1) s += __shfl_down_sync(0xffffffffu, s, o);
    __shared__ float ws[4];
    const int lane = threadIdx.x & 31, wid = threadIdx.x >> 5;
    if (lane == 0) ws[wid] = s;
    __syncthreads();
    if (threadIdx.x == 0)
        g_ctx[bc] = (ws[0] + ws[1] + ws[2] + ws[3]) * (1.0f / (HH_ * WW_));
}

// ---------------------------------------------------------------------------
// Kernel A2: MLP -> softmax -> att + aggregated bias
// ---------------------------------------------------------------------------
__global__ void mlp_kernel(const float* __restrict__ fc1_w,
                           const float* __restrict__ fc2_w,
                           const float* __restrict__ fc2_b,
                           const float* __restrict__ bias)
{
    __shared__ float ctx[CIN_];
    __shared__ float hid[HID_];
    __shared__ float att[NK_];

    const int b   = blockIdx.x;
    const int tid = threadIdx.x;   // 128 threads

    ctx[tid] = g_ctx[b * CIN_ + tid];
    __syncthreads();

    if (tid < HID_) {
        float s = 0.f;
        #pragma unroll 8
        for (int c = 0; c < CIN_; ++c) s += ctx[c] * fc1_w[tid * CIN_ + c];
        hid[tid] = fmaxf(s, 0.f);
    }
    __syncthreads();

    if (tid < NK_) {
        float s = fc2_b[tid];
        #pragma unroll
        for (int i = 0; i < HID_; ++i) s += hid[i] * fc2_w[tid * HID_ + i];
        att[tid] = s * (1.0f / TEMP_);
    }
    __syncthreads();

    if (tid == 0) {
        float m = att[0];
        #pragma unroll
        for (int k = 1; k < NK_; ++k) m = fmaxf(m, att[k]);
        float e[NK_], den = 0.f;
        #pragma unroll
        for (int k = 0; k < NK_; ++k) { e[k] = expf(att[k] - m); den += e[k]; }
        float inv = 1.0f / den;
        #pragma unroll
        for (int k = 0; k < NK_; ++k) {
            att[k] = e[k] * inv;
            g_att[b * NK_ + k] = att[k];
        }
    }
    __syncthreads();

    {
        float s = 0.f;
        #pragma unroll
        for (int k = 0; k < NK_; ++k) s += att[k] * bias[k * COUT_ + tid];
        g_aggb[b * COUT_ + tid] = s;
    }
}

// ---------------------------------------------------------------------------
// Kernel B: aggregate expert weights -> bf16 hi/lo planes.
// Layout [b][chunk(4)][tap(9)][co(128)][ci(32)]: 8KB contiguous per (b,chunk,tap).
// ---------------------------------------------------------------------------
__global__ void aggw_kernel(const float* __restrict__ weight)
{
    const int co = blockIdx.x;
    const int ci = threadIdx.x;
    const int b0 = blockIdx.y * 4;

    float wv[4][9];
    #pragma unroll
    for (int e = 0; e < 4; ++e) {
        const float* p = weight + (((size_t)e * 128 + co) * 128 + ci) * 9;
        #pragma unroll
        for (int kk = 0; kk < 9; ++kk) wv[e][kk] = p[kk];
    }
    const int chunk = ci >> 5, cil = ci & 31;
    #pragma unroll
    for (int bb = 0; bb < 4; ++bb) {
        const int b = b0 + bb;
        const float a0 = g_att[b * 4 + 0], a1 = g_att[b * 4 + 1];
        const float a2 = g_att[b * 4 + 2], a3 = g_att[b * 4 + 3];
        #pragma unroll
        for (int kk = 0; kk < 9; ++kk) {
            float v = a0 * wv[0][kk] + a1 * wv[1][kk]
                    + a2 * wv[2][kk] + a3 * wv[3][kk];
            __nv_bfloat16 hi = __float2bfloat16(v);
            __nv_bfloat16 lo = __float2bfloat16(v - __bfloat162float(hi));
            size_t off = ((((size_t)b * 4 + chunk) * 9 + kk) * 128 + co) * 32 + cil;
            g_wa_hi[off] = hi;
            g_wa_lo[off] = lo;
        }
    }
}

// ---------------------------------------------------------------------------
// Kernel C: implicit-GEMM conv via mma.sync bf16x3 (hi/lo split).
// CTA = (sample b, 2 output rows): D[128 co][128 pos], 8 warps, warp 64x32.
// K loop: 4 ci-chunks of 32 x 9 taps x 2 k16-steps x 3 plane-combos.
// smem xT: [srow 4][scol 66][ci 32] bf16, ci-stride padded to 36 (72B rows).
// smem A : [co 128][ci 32] bf16, stride 36.
// ---------------------------------------------------------------------------
#define SM_AGGB 0
#define SM_XTH  512
#define SM_XTL  (SM_XTH + 19008)   // 4*66*36*2B = 19008
#define SM_AH   (SM_XTL + 19008)
#define SM_AL   (SM_AH + 9216)     // 128*36*2B = 9216
#define SMEM_SZ (SM_AL + 9216)     // 56960 bytes

__global__ void __launch_bounds__(256, 2)
conv_kernel(const float* __restrict__ x, float* __restrict__ out)
{
    extern __shared__ __align__(16) char smem[];
    const int tid  = threadIdx.x;
    const int wid  = tid >> 5;
    const int lane = tid & 31;
    const int b    = blockIdx.y;
    const int h0   = blockIdx.x * 2;

    if (tid < 128) ((float*)(smem + SM_AGGB))[tid] = g_aggb[b * COUT_ + tid];

    // zero halo columns (scol = 0 and 65), both planes: 256 u32 writes
    {
        const int plane = tid >> 7;
        const int j     = tid & 127;
        const int ciq   = j & 15;           // 16 u32 = 32 ci
        const int scol  = ((j >> 4) & 1) ? 65 : 0;
        const int srow  = j >> 5;
        const uint32_t off = ((srow * 66 + scol) * 36 + ciq * 2) * 2;
        *(uint32_t*)(smem + (plane ? SM_XTL : SM_XTH) + off) = 0u;
    }

    float acc[4][4][4];
    #pragma unroll
    for (int mt = 0; mt < 4; ++mt)
        #pragma unroll
        for (int nt = 0; nt < 4; ++nt)
            #pragma unroll
            for (int i = 0; i < 4; ++i) acc[mt][nt][i] = 0.f;

    const int wm = wid & 1, wn = wid >> 1;
    const int g  = lane >> 2, t = lane & 3;
    const int r  = wn >> 1;
    const float* xb = x + (size_t)b * CIN_ * HH_ * WW_;

    for (int cc = 0; cc < 4; ++cc) {
        // ---- stage xT chunk: hi/lo bf16, [srow][scol][ci], coalesced reads ----
        #pragma unroll
        for (int i = 0; i < 16; ++i) {
            const int idx  = tid + i * 256;
            const int col  = idx & 63;
            const int srow = (idx >> 6) & 3;
            const int ci2  = idx >> 8;          // 0..15 (pair of ci)
            const int grow = h0 - 1 + srow;
            float v0 = 0.f, v1 = 0.f;
            if ((unsigned)grow < (unsigned)HH_) {
                const float* p = xb + ((size_t)(cc * 32 + ci2 * 2) * HH_ + grow) * WW_ + col;
                v0 = p[0];
                v1 = p[HH_ * WW_];
            }
            const __nv_bfloat16 h0b = __float2bfloat16(v0);
            const __nv_bfloat16 h1b = __float2bfloat16(v1);
            const __nv_bfloat16 l0b = __float2bfloat16(v0 - __bfloat162float(h0b));
            const __nv_bfloat16 l1b = __float2bfloat16(v1 - __bfloat162float(h1b));
            const uint32_t off = ((srow * 66 + col + 1) * 36 + ci2 * 2) * 2;
            *(uint32_t*)(smem + SM_XTH + off) = pack_bf16x2(h0b, h1b);
            *(uint32_t*)(smem + SM_XTL + off) = pack_bf16x2(l0b, l1b);
        }
        __syncthreads();

        const size_t wbase = (((size_t)b * 4 + cc) * 9) * 4096;  // elems per (b,cc,tap)=4096

        for (int tap = 0; tap < 9; ++tap) {
            // ---- stage A tiles [128co][32ci] hi/lo (8B vectors, 72B rows) ----
            {
                const uint2* sh = (const uint2*)(g_wa_hi + wbase + (size_t)tap * 4096);
                const uint2* sl = (const uint2*)(g_wa_lo + wbase + (size_t)tap * 4096);
                #pragma unroll
                for (int i = 0; i < 4; ++i) {
                    const int idx = tid + i * 256;     // 0..1023
                    const int co  = idx >> 3, ciq = idx & 7;
                    const uint32_t off = (uint32_t)co * 72 + ciq * 8;
                    *(uint2*)(smem + SM_AH + off) = sh[idx];
                    *(uint2*)(smem + SM_AL + off) = sl[idx];
                }
            }
            __syncthreads();

            const int kh = tap / 3, kw = tap - kh * 3;
            const uint32_t tapoff = (uint32_t)(kh * 66 + kw) * 72;

            #pragma unroll
            for (int ks = 0; ks < 2; ++ks) {
                const uint32_t kso = ks * 32;   // 16 ci * 2B

                // B fragments (hi & lo), 4 n-tiles
                uint32_t bh[4][2], bl[4][2];
                #pragma unroll
                for (int nt = 0; nt < 4; ++nt) {
                    const int c = ((wn & 1) << 5) + nt * 8 + g;
                    const uint32_t boff = (uint32_t)(r * 66 + c) * 72 + t * 4 + tapoff + kso;
                    bh[nt][0] = *(const uint32_t*)(smem + SM_XTH + boff);
                    bh[nt][1] = *(const uint32_t*)(smem + SM_XTH + boff + 16);
                    bl[nt][0] = *(const uint32_t*)(smem + SM_XTL + boff);
                    bl[nt][1] = *(const uint32_t*)(smem + SM_XTL + boff + 16);
                }

                #pragma unroll
                for (int mt = 0; mt < 4; ++mt) {
                    const int co = (wm << 6) + mt * 16 + g;
                    const uint32_t aoff = (uint32_t)co * 72 + t * 4 + kso;
                    uint32_t ah[4], al[4];
                    ah[0] = *(const uint32_t*)(smem + SM_AH + aoff);
                    ah[1] = *(const uint32_t*)(smem + SM_AH + aoff + 576);
                    ah[2] = *(const uint32_t*)(smem + SM_AH + aoff + 16);
                    ah[3] = *(const uint32_t*)(smem + SM_AH + aoff + 576 + 16);
                    al[0] = *(const uint32_t*)(smem + SM_AL + aoff);
                    al[1] = *(const uint32_t*)(smem + SM_AL + aoff + 576);
                    al[2] = *(const uint32_t*)(smem + SM_AL + aoff + 16);
                    al[3] = *(const uint32_t*)(smem + SM_AL + aoff + 576 + 16);

                    #pragma unroll
                    for (int nt = 0; nt < 4; ++nt) mma_bf16(acc[mt][nt], ah, bh[nt]);
                    #pragma unroll
                    for (int nt = 0; nt < 4; ++nt) mma_bf16(acc[mt][nt], ah, bl[nt]);
                    #pragma unroll
                    for (int nt = 0; nt < 4; ++nt) mma_bf16(acc[mt][nt], al, bh[nt]);
                }
            }
            __syncthreads();
        }
    }

    // ---- epilogue: bias + float2 stores straight from fragments ----
    const float* aggb_s = (const float*)(smem + SM_AGGB);
    const int rr = wn >> 1;
    #pragma unroll
    for (int mt = 0; mt < 4; ++mt) {
        const int co0 = (wm << 6) + mt * 16 + g;
        const float bv0 = aggb_s[co0];
        const float bv1 = aggb_s[co0 + 8];
        #pragma unroll
        for (int nt = 0; nt < 4; ++nt) {
            const int ccol = ((wn & 1) << 5) + nt * 8 + 2 * t;
            float2 v0 = {acc[mt][nt][0] + bv0, acc[mt][nt][1] + bv0};
            float2 v1 = {acc[mt][nt][2] + bv1, acc[mt][nt][3] + bv1};
            *(float2*)(out + ((size_t)(b * COUT_ + co0    ) * HH_ + h0 + rr) * WW_ + ccol) = v0;
            *(float2*)(out + ((size_t)(b * COUT_ + co0 + 8) * HH_ + h0 + rr) * WW_ + ccol) = v1;
        }
    }
}

// ---------------------------------------------------------------------------
extern "C" void kernel_launch(void* const* d_in, const int* in_sizes, int n_in,
                              void* d_out, int out_size)
{
    const float* x      = (const float*)d_in[0];  // [32,128,64,64]
    const float* fc1_w  = (const float*)d_in[1];  // [32,128]
    const float* fc2_w  = (const float*)d_in[2];  // [4,32]
    const float* fc2_b  = (const float*)d_in[3];  // [4]
    const float* weight = (const float*)d_in[4];  // [4,128,128,3,3]
    const float* bias   = (const float*)d_in[5];  // [4,128]
    float* out = (float*)d_out;                    // [32,128,64,64]

    cudaFuncSetAttribute(conv_kernel,
                         cudaFuncAttributeMaxDynamicSharedMemorySize, SMEM_SZ);

    pool_kernel<<<B_ * CIN_, 128>>>(x);
    mlp_kernel<<<B_, 128>>>(fc1_w, fc2_w, fc2_b, bias);
    aggw_kernel<<<dim3(COUT_, 8), 128>>>(weight);
    conv_kernel<<<dim3(HH_ / 2, B_), 256, SMEM_SZ>>>(x, out);
}

// round 9
// speedup vs baseline: 2.8024x; 1.1299x over previous
#include <cuda_runtime.h>
#include <cuda_bf16.h>
#include <cstdint>

// Problem constants
#define B_    32
#define CIN_  128
#define HH_   64
#define WW_   64
#define COUT_ 128
#define NK_   4
#define HID_  32
#define TEMP_ 34.0f

// ---------------------------------------------------------------------------
// Device scratch
// ---------------------------------------------------------------------------
__device__ float g_ctx [B_ * CIN_];
__device__ float g_att [B_ * NK_];
__device__ float g_aggb[B_ * COUT_];
// Aggregated weights, bf16 hi/lo planes, layout [b][chunk(4)][tap(9)][co(128)][ci(32)]
__device__ __align__(16) __nv_bfloat16 g_wa_hi[(size_t)B_ * 4 * 9 * 128 * 32];
__device__ __align__(16) __nv_bfloat16 g_wa_lo[(size_t)B_ * 4 * 9 * 128 * 32];

// ---------------------------------------------------------------------------
// PTX helpers (family-common: sm_80-level mma, sm_75-level ldmatrix)
// ---------------------------------------------------------------------------
__device__ __forceinline__ void mma_bf16(float* d, const uint32_t* a, const uint32_t* b) {
    asm volatile(
        "mma.sync.aligned.m16n8k16.row.col.f32.bf16.bf16.f32 "
        "{%0,%1,%2,%3}, {%4,%5,%6,%7}, {%8,%9}, {%0,%1,%2,%3};"
        : "+f"(d[0]), "+f"(d[1]), "+f"(d[2]), "+f"(d[3])
        : "r"(a[0]), "r"(a[1]), "r"(a[2]), "r"(a[3]), "r"(b[0]), "r"(b[1]));
}
__device__ __forceinline__ void ldsm_x4(uint32_t& r0, uint32_t& r1,
                                        uint32_t& r2, uint32_t& r3, uint32_t addr) {
    asm volatile("ldmatrix.sync.aligned.m8n8.x4.shared.b16 {%0,%1,%2,%3}, [%4];"
                 : "=r"(r0), "=r"(r1), "=r"(r2), "=r"(r3) : "r"(addr));
}
__device__ __forceinline__ uint32_t smem_u32(const void* p) {
    uint32_t a;
    asm("{ .reg .u64 t; cvta.to.shared.u64 t, %1; cvt.u32.u64 %0, t; }"
        : "=r"(a) : "l"(p));
    return a;
}
__device__ __forceinline__ uint32_t pack_bf16x2(__nv_bfloat16 lo, __nv_bfloat16 hi) {
    return (uint32_t)__bfloat16_as_ushort(lo) | ((uint32_t)__bfloat16_as_ushort(hi) << 16);
}

// ---------------------------------------------------------------------------
// Kernel A1: global average pool -> g_ctx
// ---------------------------------------------------------------------------
__global__ void pool_kernel(const float* __restrict__ x)
{
    const int bc = blockIdx.x;
    const float4* p = (const float4*)(x + (size_t)bc * (HH_ * WW_));
    float s = 0.f;
    #pragma unroll
    for (int i = 0; i < 8; ++i) {
        float4 v = p[threadIdx.x + (i << 7)];
        s += (v.x + v.y) + (v.z + v.w);
    }
    #pragma unroll
    for (int o = 16; o > 0; o >>= 1) s += __shfl_down_sync(0xffffffffu, s, o);
    __shared__ float ws[4];
    const int lane = threadIdx.x & 31, wid = threadIdx.x >> 5;
    if (lane == 0) ws[wid] = s;
    __syncthreads();
    if (threadIdx.x == 0)
        g_ctx[bc] = (ws[0] + ws[1] + ws[2] + ws[3]) * (1.0f / (HH_ * WW_));
}

// ---------------------------------------------------------------------------
// Kernel A2: MLP -> softmax -> att + aggregated bias
// ---------------------------------------------------------------------------
__global__ void mlp_kernel(const float* __restrict__ fc1_w,
                           const float* __restrict__ fc2_w,
                           const float* __restrict__ fc2_b,
                           const float* __restrict__ bias)
{
    __shared__ float ctx[CIN_];
    __shared__ float hid[HID_];
    __shared__ float att[NK_];

    const int b   = blockIdx.x;
    const int tid = threadIdx.x;   // 128 threads

    ctx[tid] = g_ctx[b * CIN_ + tid];
    __syncthreads();

    if (tid < HID_) {
        float s = 0.f;
        #pragma unroll 8
        for (int c = 0; c < CIN_; ++c) s += ctx[c] * fc1_w[tid * CIN_ + c];
        hid[tid] = fmaxf(s, 0.f);
    }
    __syncthreads();

    if (tid < NK_) {
        float s = fc2_b[tid];
        #pragma unroll
        for (int i = 0; i < HID_; ++i) s += hid[i] * fc2_w[tid * HID_ + i];
        att[tid] = s * (1.0f / TEMP_);
    }
    __syncthreads();

    if (tid == 0) {
        float m = att[0];
        #pragma unroll
        for (int k = 1; k < NK_; ++k) m = fmaxf(m, att[k]);
        float e[NK_], den = 0.f;
        #pragma unroll
        for (int k = 0; k < NK_; ++k) { e[k] = expf(att[k] - m); den += e[k]; }
        float inv = 1.0f / den;
        #pragma unroll
        for (int k = 0; k < NK_; ++k) {
            att[k] = e[k] * inv;
            g_att[b * NK_ + k] = att[k];
        }
    }
    __syncthreads();

    {
        float s = 0.f;
        #pragma unroll
        for (int k = 0; k < NK_; ++k) s += att[k] * bias[k * COUT_ + tid];
        g_aggb[b * COUT_ + tid] = s;
    }
}

// ---------------------------------------------------------------------------
// Kernel B: aggregate expert weights -> bf16 hi/lo planes.
// Layout [b][chunk(4)][tap(9)][co(128)][ci(32)]: 8KB contiguous per (b,chunk,tap).
// ---------------------------------------------------------------------------
__global__ void aggw_kernel(const float* __restrict__ weight)
{
    const int co = blockIdx.x;
    const int ci = threadIdx.x;
    const int b0 = blockIdx.y * 4;

    float wv[4][9];
    #pragma unroll
    for (int e = 0; e < 4; ++e) {
        const float* p = weight + (((size_t)e * 128 + co) * 128 + ci) * 9;
        #pragma unroll
        for (int kk = 0; kk < 9; ++kk) wv[e][kk] = p[kk];
    }
    const int chunk = ci >> 5, cil = ci & 31;
    #pragma unroll
    for (int bb = 0; bb < 4; ++bb) {
        const int b = b0 + bb;
        const float a0 = g_att[b * 4 + 0], a1 = g_att[b * 4 + 1];
        const float a2 = g_att[b * 4 + 2], a3 = g_att[b * 4 + 3];
        #pragma unroll
        for (int kk = 0; kk < 9; ++kk) {
            float v = a0 * wv[0][kk] + a1 * wv[1][kk]
                    + a2 * wv[2][kk] + a3 * wv[3][kk];
            __nv_bfloat16 hi = __float2bfloat16(v);
            __nv_bfloat16 lo = __float2bfloat16(v - __bfloat162float(hi));
            size_t off = ((((size_t)b * 4 + chunk) * 9 + kk) * 128 + co) * 32 + cil;
            g_wa_hi[off] = hi;
            g_wa_lo[off] = lo;
        }
    }
}

// ---------------------------------------------------------------------------
// Kernel C: implicit-GEMM conv via mma.sync bf16x3, ldmatrix fragments.
// CTA = (sample b, 2 output rows): D[128 co][128 pos], 4 warps, warp 64x64.
// smem rows padded to 80B (20-word stride -> LDSM conflict-free).
// A tiles double-buffered, prefetched one tap ahead.
// ---------------------------------------------------------------------------
#define XROW   80                          // bytes per pos-row (32 ci bf16 + pad)
#define SM_AGGB 0
#define SM_XTH  512
#define SM_XTL  (SM_XTH + 4 * 66 * XROW)   // +21120
#define SM_A0   (SM_XTL + 4 * 66 * XROW)   // buf0 hi
#define APLANE  (128 * XROW)               // 10240 per plane
#define ABUF    (2 * APLANE)               // 20480 per buffer (hi+lo)
#define SMEM_SZ (SM_A0 + 2 * ABUF)         // 83712

__global__ void __launch_bounds__(128, 2)
conv_kernel(const float* __restrict__ x, float* __restrict__ out)
{
    extern __shared__ __align__(16) char smem[];
    const uint32_t smb = smem_u32(smem);
    const int tid  = threadIdx.x;
    const int wid  = tid >> 5;
    const int lane = tid & 31;
    const int b    = blockIdx.y;
    const int h0   = blockIdx.x * 2;
    const int wm   = wid & 1;        // co half
    const int wn   = wid >> 1;       // output row within pair
    const int g    = lane >> 2, t = lane & 3;

    ((float*)(smem + SM_AGGB))[tid] = g_aggb[b * COUT_ + tid];

    // zero halo columns (scol 0 and 65), both planes
    #pragma unroll
    for (int i = 0; i < 2; ++i) {
        const int idx  = tid + i * 128;          // 0..255
        const int plane = idx >> 7;
        const int j    = idx & 127;
        const int ciq  = j & 15;
        const int scol = ((j >> 4) & 1) ? 65 : 0;
        const int srow = j >> 5;
        const uint32_t off = (uint32_t)(srow * 66 + scol) * XROW + ciq * 4;
        *(uint32_t*)(smem + (plane ? SM_XTL : SM_XTH) + off) = 0u;
    }

    float acc[4][8][4];
    #pragma unroll
    for (int mt = 0; mt < 4; ++mt)
        #pragma unroll
        for (int nt = 0; nt < 8; ++nt)
            #pragma unroll
            for (int i = 0; i < 4; ++i) acc[mt][nt][i] = 0.f;

    const float* xb = x + (size_t)b * CIN_ * HH_ * WW_;

    // per-warp ldmatrix base offsets (lane-dependent parts)
    const uint32_t a_lane = (uint32_t)(lane & 15) * XROW + (lane >> 4) * 16;
    const uint32_t b_lane = (uint32_t)(((lane >> 4) << 3) + (lane & 7)) * XROW
                          + ((lane >> 3) & 1) * 16;

    #pragma unroll 1
    for (int cc = 0; cc < 4; ++cc) {
        __syncthreads();   // xT overwrite safety
        // ---- stage xT chunk: hi/lo bf16, [srow][scol][ci32 pad40] ----
        #pragma unroll
        for (int i = 0; i < 32; ++i) {
            const int idx  = tid + i * 128;
            const int col  = idx & 63;
            const int srow = (idx >> 6) & 3;
            const int ci2  = idx >> 8;          // 0..15
            const int grow = h0 - 1 + srow;
            float v0 = 0.f, v1 = 0.f;
            if ((unsigned)grow < (unsigned)HH_) {
                const float* p = xb + ((size_t)(cc * 32 + ci2 * 2) * HH_ + grow) * WW_ + col;
                v0 = p[0];
                v1 = p[HH_ * WW_];
            }
            const __nv_bfloat16 h0b = __float2bfloat16(v0);
            const __nv_bfloat16 h1b = __float2bfloat16(v1);
            const __nv_bfloat16 l0b = __float2bfloat16(v0 - __bfloat162float(h0b));
            const __nv_bfloat16 l1b = __float2bfloat16(v1 - __bfloat162float(h1b));
            const uint32_t off = (uint32_t)(srow * 66 + col + 1) * XROW + ci2 * 4;
            *(uint32_t*)(smem + SM_XTH + off) = pack_bf16x2(h0b, h1b);
            *(uint32_t*)(smem + SM_XTL + off) = pack_bf16x2(l0b, l1b);
        }

        const size_t wbase = (((size_t)b * 4 + cc) * 9) * 4096;

        // ---- stage A tap0 into buf0 ----
        {
            const uint4* sh = (const uint4*)(g_wa_hi + wbase);
            const uint4* sl = (const uint4*)(g_wa_lo + wbase);
            #pragma unroll
            for (int i = 0; i < 4; ++i) {
                const int idx = tid + i * 128;   // 0..511 uint4
                const uint32_t off = (uint32_t)(idx >> 2) * XROW + (idx & 3) * 16;
                *(uint4*)(smem + SM_A0 + off)          = sh[idx];
                *(uint4*)(smem + SM_A0 + APLANE + off) = sl[idx];
            }
        }
        __syncthreads();

        #pragma unroll 1
        for (int tap = 0; tap < 9; ++tap) {
            const int kh = tap / 3, kw = tap - kh * 3;
            const uint32_t abase = smb + SM_A0 + (tap & 1) * ABUF
                                 + (uint32_t)(wm * 64) * XROW + a_lane;
            // stored index for output col c, tap kw is (c + kw): staging puts
            // input col at index col+1, and input col = c + kw - 1.
            const uint32_t bbase = smb + SM_XTH
                                 + (uint32_t)((wn + kh) * 66 + kw) * XROW + b_lane;

            #pragma unroll
            for (int ks = 0; ks < 2; ++ks) {
                const uint32_t kso = ks * 32;

                uint32_t bh[8][2], bl[8][2];
                #pragma unroll
                for (int q = 0; q < 4; ++q) {
                    const uint32_t ba = bbase + q * (16 * XROW) + kso;
                    ldsm_x4(bh[2*q][0], bh[2*q][1], bh[2*q+1][0], bh[2*q+1][1], ba);
                    ldsm_x4(bl[2*q][0], bl[2*q][1], bl[2*q+1][0], bl[2*q+1][1],
                            ba + (SM_XTL - SM_XTH));
                }

                #pragma unroll
                for (int mt = 0; mt < 4; ++mt) {
                    const uint32_t aa = abase + (uint32_t)(mt * 16) * XROW + kso;
                    uint32_t ah[4], al[4];
                    ldsm_x4(ah[0], ah[1], ah[2], ah[3], aa);
                    ldsm_x4(al[0], al[1], al[2], al[3], aa + APLANE);
                    #pragma unroll
                    for (int nt = 0; nt < 8; ++nt) mma_bf16(acc[mt][nt], ah, bh[nt]);
                    #pragma unroll
                    for (int nt = 0; nt < 8; ++nt) mma_bf16(acc[mt][nt], ah, bl[nt]);
                    #pragma unroll
                    for (int nt = 0; nt < 8; ++nt) mma_bf16(acc[mt][nt], al, bh[nt]);
                }
            }

            // ---- prefetch A for tap+1 into the other buffer ----
            if (tap < 8) {
                const uint4* sh = (const uint4*)(g_wa_hi + wbase + (size_t)(tap + 1) * 4096);
                const uint4* sl = (const uint4*)(g_wa_lo + wbase + (size_t)(tap + 1) * 4096);
                char* dst = smem + SM_A0 + ((tap + 1) & 1) * ABUF;
                #pragma unroll
                for (int i = 0; i < 4; ++i) {
                    const int idx = tid + i * 128;
                    const uint32_t off = (uint32_t)(idx >> 2) * XROW + (idx & 3) * 16;
                    *(uint4*)(dst + off)          = sh[idx];
                    *(uint4*)(dst + APLANE + off) = sl[idx];
                }
            }
            __syncthreads();
        }
    }

    // ---- epilogue: bias + float2 stores straight from fragments ----
    const float* aggb_s = (const float*)(smem + SM_AGGB);
    #pragma unroll
    for (int mt = 0; mt < 4; ++mt) {
        const int co0 = (wm << 6) + mt * 16 + g;
        const float bv0 = aggb_s[co0];
        const float bv1 = aggb_s[co0 + 8];
        #pragma unroll
        for (int nt = 0; nt < 8; ++nt) {
            const int ccol = nt * 8 + 2 * t;
            float2 v0 = {acc[mt][nt][0] + bv0, acc[mt][nt][1] + bv0};
            float2 v1 = {acc[mt][nt][2] + bv1, acc[mt][nt][3] + bv1};
            *(float2*)(out + ((size_t)(b * COUT_ + co0    ) * HH_ + h0 + wn) * WW_ + ccol) = v0;
            *(float2*)(out + ((size_t)(b * COUT_ + co0 + 8) * HH_ + h0 + wn) * WW_ + ccol) = v1;
        }
    }
}

// ---------------------------------------------------------------------------
extern "C" void kernel_launch(void* const* d_in, const int* in_sizes, int n_in,
                              void* d_out, int out_size)
{
    const float* x      = (const float*)d_in[0];  // [32,128,64,64]
    const float* fc1_w  = (const float*)d_in[1];  // [32,128]
    const float* fc2_w  = (const float*)d_in[2];  // [4,32]
    const float* fc2_b  = (const float*)d_in[3];  // [4]
    const float* weight = (const float*)d_in[4];  // [4,128,128,3,3]
    const float* bias   = (const float*)d_in[5];  // [4,128]
    float* out = (float*)d_out;                    // [32,128,64,64]

    cudaFuncSetAttribute(conv_kernel,
                         cudaFuncAttributeMaxDynamicSharedMemorySize, SMEM_SZ);

    pool_kernel<<<B_ * CIN_, 128>>>(x);
    mlp_kernel<<<B_, 128>>>(fc1_w, fc2_w, fc2_b, bias);
    aggw_kernel<<<dim3(COUT_, 8), 128>>>(weight);
    conv_kernel<<<dim3(HH_ / 2, B_), 128, SMEM_SZ>>>(x, out);
}

// round 11
// speedup vs baseline: 3.1428x; 1.1215x over previous
#include <cuda_runtime.h>
#include <cuda_bf16.h>
#include <cstdint>

// Problem constants
#define B_    32
#define CIN_  128
#define HH_   64
#define WW_   64
#define COUT_ 128
#define NK_   4
#define HID_  32
#define TEMP_ 34.0f

// ---------------------------------------------------------------------------
// Device scratch
// ---------------------------------------------------------------------------
__device__ float g_ctx [B_ * CIN_];
__device__ float g_att [B_ * NK_];
__device__ float g_aggb[B_ * COUT_];
// Aggregated weights, bf16 hi/lo planes, layout [b][chunk(4)][tap(9)][co(128)][ci(32)]
__device__ __align__(16) __nv_bfloat16 g_wa_hi[(size_t)B_ * 4 * 9 * 128 * 32];
__device__ __align__(16) __nv_bfloat16 g_wa_lo[(size_t)B_ * 4 * 9 * 128 * 32];

// ---------------------------------------------------------------------------
// PTX helpers (family-common: sm_80 mma + cp.async, sm_75 ldmatrix)
// ---------------------------------------------------------------------------
__device__ __forceinline__ void mma_bf16(float* d, const uint32_t* a, const uint32_t* b) {
    asm volatile(
        "mma.sync.aligned.m16n8k16.row.col.f32.bf16.bf16.f32 "
        "{%0,%1,%2,%3}, {%4,%5,%6,%7}, {%8,%9}, {%0,%1,%2,%3};"
        : "+f"(d[0]), "+f"(d[1]), "+f"(d[2]), "+f"(d[3])
        : "r"(a[0]), "r"(a[1]), "r"(a[2]), "r"(a[3]), "r"(b[0]), "r"(b[1]));
}
__device__ __forceinline__ void ldsm_x4(uint32_t& r0, uint32_t& r1,
                                        uint32_t& r2, uint32_t& r3, uint32_t addr) {
    asm volatile("ldmatrix.sync.aligned.m8n8.x4.shared.b16 {%0,%1,%2,%3}, [%4];"
                 : "=r"(r0), "=r"(r1), "=r"(r2), "=r"(r3) : "r"(addr));
}
__device__ __forceinline__ uint32_t smem_u32(const void* p) {
    uint32_t a;
    asm("{ .reg .u64 t; cvta.to.shared.u64 t, %1; cvt.u32.u64 %0, t; }"
        : "=r"(a) : "l"(p));
    return a;
}
__device__ __forceinline__ uint32_t pack_bf16x2(__nv_bfloat16 lo, __nv_bfloat16 hi) {
    return (uint32_t)__bfloat16_as_ushort(lo) | ((uint32_t)__bfloat16_as_ushort(hi) << 16);
}
__device__ __forceinline__ void cp16(uint32_t dst, const void* src) {
    asm volatile("cp.async.cg.shared.global [%0], [%1], 16;"
                 :: "r"(dst), "l"(src) : "memory");
}
__device__ __forceinline__ void cp_commit() {
    asm volatile("cp.async.commit_group;" ::: "memory");
}
__device__ __forceinline__ void cp_wait_all() {
    asm volatile("cp.async.wait_group 0;" ::: "memory");
}

// ---------------------------------------------------------------------------
// Kernel A1: global average pool -> g_ctx
// ---------------------------------------------------------------------------
__global__ void pool_kernel(const float* __restrict__ x)
{
    const int bc = blockIdx.x;
    const float4* p = (const float4*)(x + (size_t)bc * (HH_ * WW_));
    float s = 0.f;
    #pragma unroll
    for (int i = 0; i < 8; ++i) {
        float4 v = p[threadIdx.x + (i << 7)];
        s += (v.x + v.y) + (v.z + v.w);
    }
    #pragma unroll
    for (int o = 16; o > 0; o >>= 1) s += __shfl_down_sync(0xffffffffu, s, o);
    __shared__ float ws[4];
    const int lane = threadIdx.x & 31, wid = threadIdx.x >> 5;
    if (lane == 0) ws[wid] = s;
    __syncthreads();
    if (threadIdx.x == 0)
        g_ctx[bc] = (ws[0] + ws[1] + ws[2] + ws[3]) * (1.0f / (HH_ * WW_));
}

// ---------------------------------------------------------------------------
// Kernel A2: MLP -> softmax -> att + aggregated bias
// ---------------------------------------------------------------------------
__global__ void mlp_kernel(const float* __restrict__ fc1_w,
                           const float* __restrict__ fc2_w,
                           const float* __restrict__ fc2_b,
                           const float* __restrict__ bias)
{
    __shared__ float ctx[CIN_];
    __shared__ float hid[HID_];
    __shared__ float att[NK_];

    const int b   = blockIdx.x;
    const int tid = threadIdx.x;   // 128 threads

    ctx[tid] = g_ctx[b * CIN_ + tid];
    __syncthreads();

    if (tid < HID_) {
        float s = 0.f;
        #pragma unroll 8
        for (int c = 0; c < CIN_; ++c) s += ctx[c] * fc1_w[tid * CIN_ + c];
        hid[tid] = fmaxf(s, 0.f);
    }
    __syncthreads();

    if (tid < NK_) {
        float s = fc2_b[tid];
        #pragma unroll
        for (int i = 0; i < HID_; ++i) s += hid[i] * fc2_w[tid * HID_ + i];
        att[tid] = s * (1.0f / TEMP_);
    }
    __syncthreads();

    if (tid == 0) {
        float m = att[0];
        #pragma unroll
        for (int k = 1; k < NK_; ++k) m = fmaxf(m, att[k]);
        float e[NK_], den = 0.f;
        #pragma unroll
        for (int k = 0; k < NK_; ++k) { e[k] = expf(att[k] - m); den += e[k]; }
        float inv = 1.0f / den;
        #pragma unroll
        for (int k = 0; k < NK_; ++k) {
            att[k] = e[k] * inv;
            g_att[b * NK_ + k] = att[k];
        }
    }
    __syncthreads();

    {
        float s = 0.f;
        #pragma unroll
        for (int k = 0; k < NK_; ++k) s += att[k] * bias[k * COUT_ + tid];
        g_aggb[b * COUT_ + tid] = s;
    }
}

// ---------------------------------------------------------------------------
// Kernel B: aggregate expert weights -> bf16 hi/lo planes.
// Layout [b][chunk(4)][tap(9)][co(128)][ci(32)]: 8KB contiguous per (b,chunk,tap).
// ---------------------------------------------------------------------------
__global__ void aggw_kernel(const float* __restrict__ weight)
{
    const int co = blockIdx.x;
    const int ci = threadIdx.x;
    const int b0 = blockIdx.y * 4;

    float wv[4][9];
    #pragma unroll
    for (int e = 0; e < 4; ++e) {
        const float* p = weight + (((size_t)e * 128 + co) * 128 + ci) * 9;
        #pragma unroll
        for (int kk = 0; kk < 9; ++kk) wv[e][kk] = p[kk];
    }
    const int chunk = ci >> 5, cil = ci & 31;
    #pragma unroll
    for (int bb = 0; bb < 4; ++bb) {
        const int b = b0 + bb;
        const float a0 = g_att[b * 4 + 0], a1 = g_att[b * 4 + 1];
        const float a2 = g_att[b * 4 + 2], a3 = g_att[b * 4 + 3];
        #pragma unroll
        for (int kk = 0; kk < 9; ++kk) {
            float v = a0 * wv[0][kk] + a1 * wv[1][kk]
                    + a2 * wv[2][kk] + a3 * wv[3][kk];
            __nv_bfloat16 hi = __float2bfloat16(v);
            __nv_bfloat16 lo = __float2bfloat16(v - __bfloat162float(hi));
            size_t off = ((((size_t)b * 4 + chunk) * 9 + kk) * 128 + co) * 32 + cil;
            g_wa_hi[off] = hi;
            g_wa_lo[off] = lo;
        }
    }
}

// ---------------------------------------------------------------------------
// Kernel C: implicit-GEMM conv via mma.sync bf16x3, ldmatrix fragments.
// CTA = (sample b, 2 output rows): D[128 co][128 pos], 4 warps, warp 64x64.
// smem rows padded to 80B (20-word stride -> LDSM conflict-free).
// A tiles double-buffered via cp.async, prefetched one tap ahead (parity over
// global tap counter gt = cc*9+tap; 9 odd makes cross-chunk parity work).
// ---------------------------------------------------------------------------
#define XROW   80                          // bytes per pos-row (32 ci bf16 + pad)
#define SM_AGGB 0
#define SM_XTH  512
#define SM_XTL  (SM_XTH + 4 * 66 * XROW)   // +21120
#define SM_A0   (SM_XTL + 4 * 66 * XROW)   // buf0 hi
#define APLANE  (128 * XROW)               // 10240 per plane
#define ABUF    (2 * APLANE)               // 20480 per buffer (hi+lo)
#define SMEM_SZ (SM_A0 + 2 * ABUF)         // 83712

__global__ void __launch_bounds__(128, 2)
conv_kernel(const float* __restrict__ x, float* __restrict__ out)
{
    extern __shared__ __align__(16) char smem[];
    const uint32_t smb = smem_u32(smem);
    const int tid  = threadIdx.x;
    const int wid  = tid >> 5;
    const int lane = tid & 31;
    const int b    = blockIdx.y;
    const int h0   = blockIdx.x * 2;
    const int wm   = wid & 1;        // co half
    const int wn   = wid >> 1;       // output row within pair
    const int g    = lane >> 2, t = lane & 3;

    ((float*)(smem + SM_AGGB))[tid] = g_aggb[b * COUT_ + tid];

    // zero halo columns (scol 0 and 65), both planes
    #pragma unroll
    for (int i = 0; i < 2; ++i) {
        const int idx  = tid + i * 128;          // 0..255
        const int plane = idx >> 7;
        const int j    = idx & 127;
        const int ciq  = j & 15;
        const int scol = ((j >> 4) & 1) ? 65 : 0;
        const int srow = j >> 5;
        const uint32_t off = (uint32_t)(srow * 66 + scol) * XROW + ciq * 4;
        *(uint32_t*)(smem + (plane ? SM_XTL : SM_XTH) + off) = 0u;
    }

    float acc[4][8][4];
    #pragma unroll
    for (int mt = 0; mt < 4; ++mt)
        #pragma unroll
        for (int nt = 0; nt < 8; ++nt)
            #pragma unroll
            for (int i = 0; i < 4; ++i) acc[mt][nt][i] = 0.f;

    const float* xb = x + (size_t)b * CIN_ * HH_ * WW_;
    const size_t wb_b = (size_t)b * 4 * 9 * 4096;   // base elem offset for sample

    // per-thread cp.async A-tile offsets (4 x uint4 per plane)
    uint32_t cpoff[4];
    #pragma unroll
    for (int i = 0; i < 4; ++i) {
        const int idx = tid + i * 128;   // 0..511 uint4
        cpoff[i] = (uint32_t)(idx >> 2) * XROW + (idx & 3) * 16;
    }

    // issue A prefetch for gt=0 into buf0
    #pragma unroll
    for (int i = 0; i < 4; ++i) {
        const int idx = tid + i * 128;
        cp16(smb + SM_A0 + cpoff[i],          (const char*)(g_wa_hi + wb_b) + idx * 16);
        cp16(smb + SM_A0 + APLANE + cpoff[i], (const char*)(g_wa_lo + wb_b) + idx * 16);
    }
    cp_commit();

    // per-warp ldmatrix base offsets (lane-dependent parts)
    const uint32_t a_lane = (uint32_t)(lane & 15) * XROW + (lane >> 4) * 16;
    const uint32_t b_lane = (uint32_t)(((lane >> 4) << 3) + (lane & 7)) * XROW
                          + ((lane >> 3) & 1) * 16;

    #pragma unroll 1
    for (int cc = 0; cc < 4; ++cc) {
        // ---- stage xT chunk: hi/lo bf16, [srow][scol][ci32 pad40] ----
        // (safe vs prior-tap reads: every tap ends with __syncthreads)
        #pragma unroll
        for (int i = 0; i < 32; ++i) {
            const int idx  = tid + i * 128;
            const int col  = idx & 63;
            const int srow = (idx >> 6) & 3;
            const int ci2  = idx >> 8;          // 0..15
            const int grow = h0 - 1 + srow;
            float v0 = 0.f, v1 = 0.f;
            if ((unsigned)grow < (unsigned)HH_) {
                const float* p = xb + ((size_t)(cc * 32 + ci2 * 2) * HH_ + grow) * WW_ + col;
                v0 = p[0];
                v1 = p[HH_ * WW_];
            }
            const __nv_bfloat16 h0b = __float2bfloat16(v0);
            const __nv_bfloat16 h1b = __float2bfloat16(v1);
            const __nv_bfloat16 l0b = __float2bfloat16(v0 - __bfloat162float(h0b));
            const __nv_bfloat16 l1b = __float2bfloat16(v1 - __bfloat162float(h1b));
            const uint32_t off = (uint32_t)(srow * 66 + col + 1) * XROW + ci2 * 4;
            *(uint32_t*)(smem + SM_XTH + off) = pack_bf16x2(h0b, h1b);
            *(uint32_t*)(smem + SM_XTL + off) = pack_bf16x2(l0b, l1b);
        }
        cp_wait_all();        // A tile for this chunk's tap0 is resident
        __syncthreads();

        #pragma unroll 1
        for (int tap = 0; tap < 9; ++tap) {
            const int gt = cc * 9 + tap;
            const int kh = tap / 3, kw = tap - kh * 3;

            // ---- prefetch A for gt+1 into the other parity buffer ----
            if (gt < 35) {
                const size_t src = wb_b + (size_t)(gt + 1) * 4096;
                const uint32_t dst = smb + SM_A0 + (uint32_t)(((gt + 1) & 1) * ABUF);
                #pragma unroll
                for (int i = 0; i < 4; ++i) {
                    const int idx = tid + i * 128;
                    cp16(dst + cpoff[i],          (const char*)(g_wa_hi + src) + idx * 16);
                    cp16(dst + APLANE + cpoff[i], (const char*)(g_wa_lo + src) + idx * 16);
                }
                cp_commit();
            }

            const uint32_t abase = smb + SM_A0 + (uint32_t)((gt & 1) * ABUF)
                                 + (uint32_t)(wm * 64) * XROW + a_lane;
            // stored index for output col c, tap kw is (c + kw): staging puts
            // input col at index col+1, and input col = c + kw - 1.
            const uint32_t bbase = smb + SM_XTH
                                 + (uint32_t)((wn + kh) * 66 + kw) * XROW + b_lane;

            #pragma unroll
            for (int ks = 0; ks < 2; ++ks) {
                const uint32_t kso = ks * 32;

                uint32_t bh[8][2], bl[8][2];
                #pragma unroll
                for (int q = 0; q < 4; ++q) {
                    const uint32_t ba = bbase + q * (16 * XROW) + kso;
                    ldsm_x4(bh[2*q][0], bh[2*q][1], bh[2*q+1][0], bh[2*q+1][1], ba);
                    ldsm_x4(bl[2*q][0], bl[2*q][1], bl[2*q+1][0], bl[2*q+1][1],
                            ba + (SM_XTL - SM_XTH));
                }

                #pragma unroll
                for (int mt = 0; mt < 4; ++mt) {
                    const uint32_t aa = abase + (uint32_t)(mt * 16) * XROW + kso;
                    uint32_t ah[4], al[4];
                    ldsm_x4(ah[0], ah[1], ah[2], ah[3], aa);
                    ldsm_x4(al[0], al[1], al[2], al[3], aa + APLANE);
                    #pragma unroll
                    for (int nt = 0; nt < 8; ++nt) mma_bf16(acc[mt][nt], ah, bh[nt]);
                    #pragma unroll
                    for (int nt = 0; nt < 8; ++nt) mma_bf16(acc[mt][nt], ah, bl[nt]);
                    #pragma unroll
                    for (int nt = 0; nt < 8; ++nt) mma_bf16(acc[mt][nt], al, bh[nt]);
                }
            }

            cp_wait_all();     // next A tile landed (hidden under the MMAs)
            __syncthreads();
        }
    }

    // ---- epilogue: bias + float2 stores straight from fragments ----
    const float* aggb_s = (const float*)(smem + SM_AGGB);
    #pragma unroll
    for (int mt = 0; mt < 4; ++mt) {
        const int co0 = (wm << 6) + mt * 16 + g;
        const float bv0 = aggb_s[co0];
        const float bv1 = aggb_s[co0 + 8];
        #pragma unroll
        for (int nt = 0; nt < 8; ++nt) {
            const int ccol = nt * 8 + 2 * t;
            float2 v0 = {acc[mt][nt][0] + bv0, acc[mt][nt][1] + bv0};
            float2 v1 = {acc[mt][nt][2] + bv1, acc[mt][nt][3] + bv1};
            *(float2*)(out + ((size_t)(b * COUT_ + co0    ) * HH_ + h0 + wn) * WW_ + ccol) = v0;
            *(float2*)(out + ((size_t)(b * COUT_ + co0 + 8) * HH_ + h0 + wn) * WW_ + ccol) = v1;
        }
    }
}

// ---------------------------------------------------------------------------
extern "C" void kernel_launch(void* const* d_in, const int* in_sizes, int n_in,
                              void* d_out, int out_size)
{
    const float* x      = (const float*)d_in[0];  // [32,128,64,64]
    const float* fc1_w  = (const float*)d_in[1];  // [32,128]
    const float* fc2_w  = (const float*)d_in[2];  // [4,32]
    const float* fc2_b  = (const float*)d_in[3];  // [4]
    const float* weight = (const float*)d_in[4];  // [4,128,128,3,3]
    const float* bias   = (const float*)d_in[5];  // [4,128]
    float* out = (float*)d_out;                    // [32,128,64,64]

    cudaFuncSetAttribute(conv_kernel,
                         cudaFuncAttributeMaxDynamicSharedMemorySize, SMEM_SZ);

    pool_kernel<<<B_ * CIN_, 128>>>(x);
    mlp_kernel<<<B_, 128>>>(fc1_w, fc2_w, fc2_b, bias);
    aggw_kernel<<<dim3(COUT_, 8), 128>>>(weight);
    conv_kernel<<<dim3(HH_ / 2, B_), 128, SMEM_SZ>>>(x, out);
}